// round 1
// baseline (speedup 1.0000x reference)
#include <cuda_runtime.h>
#include <cuda_fp16.h>

#define BB 128
#define NN 2592
#define CC 16
#define LL 64

// ---------------- device scratch (no allocations allowed) ----------------
__device__ __half2 g_uhat[(size_t)BB * NN * (LL / 2)]; // [b][n][l] fp16, 42.5MB
__device__ float   g_nsq[(size_t)BB * NN];             // sum_l u_hat^2
__device__ float   g_v[BB * LL];                       // v_j scratch
__device__ float   g_c[NN];                            // softmax coupling
__device__ float   g_b[NN];                            // routing logits
__device__ float   g_A[NN];                            // agreement accumulator

// ---------------- init: c = 1/N, b = 0, A = 0 ----------------
__global__ void k_init() {
    int i = blockIdx.x * blockDim.x + threadIdx.x;
    if (i < NN) {
        g_c[i] = 1.0f / (float)NN;
        g_b[i] = 0.0f;
        g_A[i] = 0.0f;
    }
}

// ---------------- u_hat + per-(b,n) squared L-norm ----------------
// one block per n; 8 warps, each warp owns 16 consecutive b's; lane owns l=2*lane,2*lane+1
__global__ __launch_bounds__(256) void k_uhat(const float* __restrict__ x,
                                              const float* __restrict__ W) {
    const int n = blockIdx.x;
    __shared__ float sX[BB * CC]; // x[:, n, :]  (8KB)
    for (int i = threadIdx.x; i < BB * CC; i += 256) {
        int b = i >> 4, c = i & 15;
        sX[i] = x[(size_t)b * (NN * CC) + n * CC + c];
    }
    const int lane = threadIdx.x & 31;
    const int w    = threadIdx.x >> 5;
    const int l0   = lane * 2;
    const float4* W4 = reinterpret_cast<const float4*>(W + (size_t)n * LL * CC);
    // two W rows (l0, l0+1), 16 floats each, held in registers
    float4 wa0 = W4[l0 * 4 + 0], wa1 = W4[l0 * 4 + 1], wa2 = W4[l0 * 4 + 2], wa3 = W4[l0 * 4 + 3];
    float4 wb0 = W4[l0 * 4 + 4], wb1 = W4[l0 * 4 + 5], wb2 = W4[l0 * 4 + 6], wb3 = W4[l0 * 4 + 7];
    __syncthreads();

    __half2* Uout = g_uhat + (size_t)n * 32;
#pragma unroll 4
    for (int j = 0; j < 16; j++) {
        int b = w * 16 + j;
        const float4* xv = reinterpret_cast<const float4*>(&sX[b * CC]);
        float4 x0 = xv[0], x1 = xv[1], x2 = xv[2], x3 = xv[3];
        float a0 = wa0.x * x0.x + wa0.y * x0.y + wa0.z * x0.z + wa0.w * x0.w
                 + wa1.x * x1.x + wa1.y * x1.y + wa1.z * x1.z + wa1.w * x1.w
                 + wa2.x * x2.x + wa2.y * x2.y + wa2.z * x2.z + wa2.w * x2.w
                 + wa3.x * x3.x + wa3.y * x3.y + wa3.z * x3.z + wa3.w * x3.w;
        float a1 = wb0.x * x0.x + wb0.y * x0.y + wb0.z * x0.z + wb0.w * x0.w
                 + wb1.x * x1.x + wb1.y * x1.y + wb1.z * x1.z + wb1.w * x1.w
                 + wb2.x * x2.x + wb2.y * x2.y + wb2.z * x2.z + wb2.w * x2.w
                 + wb3.x * x3.x + wb3.y * x3.y + wb3.z * x3.z + wb3.w * x3.w;
        Uout[(size_t)b * NN * 32 + lane] = __floats2half2_rn(a0, a1);
        // warp-reduce squared norm over the 64 l's
        float p = a0 * a0 + a1 * a1;
#pragma unroll
        for (int o = 16; o; o >>= 1) p += __shfl_xor_sync(0xffffffffu, p, o);
        if (lane == 0) g_nsq[(size_t)b * NN + n] = p;
    }
}

__device__ __forceinline__ float squash1(float s) {
    float sq = s * s;
    return sq * s / ((1.0f + sq) * sqrtf(sq));
}

// ---------------- s_j = sum_n c[n]*u_hat ; v = squash(s) ----------------
// one block per b; 16 warps stride over n; lane owns l=2*lane,2*lane+1
__global__ __launch_bounds__(512) void k_s(float* __restrict__ extout) {
    const int b    = blockIdx.x;
    const int lane = threadIdx.x & 31;
    const int wg   = threadIdx.x >> 5; // 0..15
    const __half2* U = g_uhat + (size_t)b * NN * 32;
    float ax = 0.f, ay = 0.f;
#pragma unroll 4
    for (int n = wg; n < NN; n += 16) {
        float cn = __ldg(&g_c[n]);
        float2 u = __half22float2(U[n * 32 + lane]);
        ax += cn * u.x;
        ay += cn * u.y;
    }
    __shared__ float2 red[16][32];
    red[wg][lane].x = ax;
    red[wg][lane].y = ay;
    __syncthreads();
    if (threadIdx.x < 32) {
        float sx = 0.f, sy = 0.f;
#pragma unroll
        for (int k = 0; k < 16; k++) { sx += red[k][threadIdx.x].x; sy += red[k][threadIdx.x].y; }
        float vx = squash1(sx);
        float vy = squash1(sy);
        float* dst = extout ? extout : g_v;
        dst[b * LL + 2 * threadIdx.x]     = vx;
        dst[b * LL + 2 * threadIdx.x + 1] = vy;
        if (extout) { // keep g_v coherent too (harmless, tiny)
            g_v[b * LL + 2 * threadIdx.x]     = vx;
            g_v[b * LL + 2 * threadIdx.x + 1] = vy;
        }
    }
}

// ---------------- a_ij = u_hat . v ; A[n] += mean_b ----------------
__global__ __launch_bounds__(128) void k_a() {
    const int b = blockIdx.y;
    const int n = blockIdx.x * blockDim.x + threadIdx.x;
    __shared__ float sv[LL];
    if (threadIdx.x < LL) sv[threadIdx.x] = g_v[b * LL + threadIdx.x];
    __syncthreads();
    if (n >= NN) return;
    const float4* U4 = reinterpret_cast<const float4*>(g_uhat + ((size_t)b * NN + n) * 32);
    float acc = 0.f;
#pragma unroll
    for (int k = 0; k < 8; k++) {
        float4 q = U4[k];
        __half2 h0 = *reinterpret_cast<__half2*>(&q.x);
        __half2 h1 = *reinterpret_cast<__half2*>(&q.y);
        __half2 h2 = *reinterpret_cast<__half2*>(&q.z);
        __half2 h3 = *reinterpret_cast<__half2*>(&q.w);
        float2 p0 = __half22float2(h0), p1 = __half22float2(h1);
        float2 p2 = __half22float2(h2), p3 = __half22float2(h3);
        int l = k * 8;
        acc += p0.x * sv[l]     + p0.y * sv[l + 1];
        acc += p1.x * sv[l + 2] + p1.y * sv[l + 3];
        acc += p2.x * sv[l + 4] + p2.y * sv[l + 5];
        acc += p3.x * sv[l + 6] + p3.y * sv[l + 7];
    }
    atomicAdd(&g_A[n], acc * (1.0f / (float)BB));
}

// ---------------- b += A ; c = softmax(b) ; A = 0 ----------------
__global__ __launch_bounds__(1024) void k_softmax() {
    __shared__ float sb[NN];
    __shared__ float sred[32];
    __shared__ float sbroad;
    const int t = threadIdx.x, lane = t & 31, wid = t >> 5;
    float mx = -1e30f;
    for (int n = t; n < NN; n += 1024) {
        float bn = g_b[n] + g_A[n];
        g_b[n] = bn;
        g_A[n] = 0.0f;
        sb[n] = bn;
        mx = fmaxf(mx, bn);
    }
#pragma unroll
    for (int o = 16; o; o >>= 1) mx = fmaxf(mx, __shfl_xor_sync(0xffffffffu, mx, o));
    if (lane == 0) sred[wid] = mx;
    __syncthreads();
    if (t == 0) {
        float m = sred[0];
        for (int k = 1; k < 32; k++) m = fmaxf(m, sred[k]);
        sbroad = m;
    }
    __syncthreads();
    const float gmax = sbroad;
    float s = 0.f;
    for (int n = t; n < NN; n += 1024) {
        float e = expf(sb[n] - gmax);
        sb[n] = e;
        s += e;
    }
#pragma unroll
    for (int o = 16; o; o >>= 1) s += __shfl_xor_sync(0xffffffffu, s, o);
    __syncthreads();
    if (lane == 0) sred[wid] = s;
    __syncthreads();
    if (t == 0) {
        float tot = 0.f;
        for (int k = 0; k < 32; k++) tot += sred[k];
        sbroad = 1.0f / tot;
    }
    __syncthreads();
    const float inv = sbroad;
    for (int n = t; n < NN; n += 1024) g_c[n] = sb[n] * inv;
}

// ---------------- u_norm = c[n]*sqrt(nsq) ; convtranspose2d ----------------
// one block per b; warp = one (ky,kx) parity class half => all weight LDS broadcast
__global__ __launch_bounds__(256) void k_conv(const float* __restrict__ conv_w,
                                              const float* __restrict__ conv_b,
                                              float* __restrict__ out) {
    const int b = blockIdx.x;
    __shared__ float sU[NN];          // u_norm[b, ic, iy, ix]
    __shared__ float sW[4 * 64 * 32]; // [kk][oc][ic]
    __shared__ float sB[64];
    for (int i = threadIdx.x; i < NN; i += 256)
        sU[i] = g_c[i] * sqrtf(g_nsq[(size_t)b * NN + i]);
    for (int i = threadIdx.x; i < 8192; i += 256) {
        int kk = i >> 11, oc = (i >> 5) & 63, ic = i & 31;
        sW[i] = conv_w[(ic * 64 + oc) * 4 + kk]; // (ic,oc,ky,kx), kk = ky*2+kx
    }
    if (threadIdx.x < 64) sB[threadIdx.x] = conv_b[threadIdx.x];
    __syncthreads();

    const int w    = threadIdx.x >> 5;
    const int lane = threadIdx.x & 31;
    const int kk   = w & 3;          // parity class
    const int ky   = kk >> 1, kx = kk & 1;
    const int half = w >> 2;
    const int r = half * 4 + (lane >> 3); // 0..7
    const int s = lane & 7;               // 0..7
    // oy = 2r + (1-ky); iy = r + (1-ky); same for x
    const int oy = 2 * r + (ky ? 0 : 1);
    const int ox = 2 * s + (kx ? 0 : 1);
    const int iy = r + (ky ? 0 : 1);
    const int ix = s + (kx ? 0 : 1);

    float u[32];
#pragma unroll
    for (int ic = 0; ic < 32; ic++) u[ic] = sU[ic * 81 + iy * 9 + ix];

    const float4* sW4 = reinterpret_cast<const float4*>(&sW[kk * 2048]);
    float* ob = out + (size_t)b * 64 * 256 + oy * 16 + ox;
#pragma unroll 4
    for (int oc = 0; oc < 64; oc++) {
        float acc = sB[oc];
#pragma unroll
        for (int q = 0; q < 8; q++) {
            float4 wv = sW4[oc * 8 + q];
            acc += wv.x * u[4 * q] + wv.y * u[4 * q + 1] + wv.z * u[4 * q + 2] + wv.w * u[4 * q + 3];
        }
        ob[oc * 256] = acc;
    }
}

// ---------------- launch ----------------
extern "C" void kernel_launch(void* const* d_in, const int* in_sizes, int n_in,
                              void* d_out, int out_size) {
    const float* x  = (const float*)d_in[0]; // (B, N, C)
    const float* W  = (const float*)d_in[1]; // (1, N, 1, L, C)
    const float* cw = (const float*)d_in[2]; // (32, 64, 2, 2)
    const float* cb = (const float*)d_in[3]; // (64,)
    float* out = (float*)d_out;              // [v_j (B*L)] ++ [out_img (B*64*256)]

    k_init<<<(NN + 255) / 256, 256>>>();
    k_uhat<<<NN, 256>>>(x, W);

    dim3 agrid((NN + 127) / 128, BB);

    // iter 0
    k_s<<<BB, 512>>>((float*)nullptr);
    k_a<<<agrid, 128>>>();
    k_softmax<<<1, 1024>>>();
    // iter 1
    k_s<<<BB, 512>>>((float*)nullptr);
    k_a<<<agrid, 128>>>();
    k_softmax<<<1, 1024>>>();
    // iter 2: v_j -> output
    k_s<<<BB, 512>>>(out);
    // u_norm + conv transpose -> output
    k_conv<<<BB, 256>>>(cw, cb, out + BB * LL);
}